// round 9
// baseline (speedup 1.0000x reference)
#include <cuda_runtime.h>
#include <cstdint>

#define S_LEN   4096
#define DMODEL  1024
#define NHEADS  16
#define DK      64

// Scratch (allocation-free rule: __device__ globals)
__device__ float g_q [S_LEN * DMODEL];
__device__ float g_k [S_LEN * DMODEL];
__device__ float g_v [S_LEN * DMODEL];
__device__ float g_vT[S_LEN * DMODEL];          // per-head transposed+permuted V
__device__ float g_ao[S_LEN * DMODEL];
__device__ float g_xr[S_LEN * DMODEL];          // tf32-rounded x
__device__ float g_wr[4][DMODEL * DMODEL];      // tf32-rounded (row-permuted for q,k) weights

// ---------------------------------------------------------------------------
// helpers
// ---------------------------------------------------------------------------
__device__ __forceinline__ float f2tf(float f) {
    uint32_t r;
    asm("cvt.rna.tf32.f32 %0, %1;" : "=r"(r) : "f"(f));
    return __uint_as_float(r);
}

__device__ __forceinline__ void mma8(float* d, const uint32_t* a, const uint32_t* b) {
    asm volatile(
        "mma.sync.aligned.m16n8k8.row.col.f32.tf32.tf32.f32 "
        "{%0,%1,%2,%3}, {%4,%5,%6,%7}, {%8,%9}, {%0,%1,%2,%3};"
        : "+f"(d[0]), "+f"(d[1]), "+f"(d[2]), "+f"(d[3])
        : "r"(a[0]), "r"(a[1]), "r"(a[2]), "r"(a[3]), "r"(b[0]), "r"(b[1]));
}

__device__ __forceinline__ void cpa16(uint32_t dst, const void* src) {
    asm volatile("cp.async.cg.shared.global [%0], [%1], 16;" :: "r"(dst), "l"(src));
}
#define CPA_COMMIT() asm volatile("cp.async.commit_group;")
#define CPA_WAIT0()  asm volatile("cp.async.wait_group 0;" ::: "memory")

// involution permutation within a 64-block: p(j) = (j&7)*8 + (j>>3)
__device__ __forceinline__ int p64(int j) { return ((j & 7) << 3) | (j >> 3); }

// ---------------------------------------------------------------------------
// tf32 rounding pass (natural layout)
// ---------------------------------------------------------------------------
__global__ void __launch_bounds__(256) round4(const float* __restrict__ in,
                                              float* __restrict__ out, int n4) {
    int i = blockIdx.x * blockDim.x + threadIdx.x;
    if (i < n4) {
        float4 v = ((const float4*)in)[i];
        ((float4*)out)[i] = make_float4(f2tf(v.x), f2tf(v.y), f2tf(v.z), f2tf(v.w));
    }
}

// tf32 rounding + ROW permutation within each 64-row block (for Wq, Wk):
// out[n][:] = tf32(in[(n&~63) | p64(n&63)][:])  -> q/k columns come out permuted
// FIX vs R7: one block per ROW; 256 threads x float4 covers all 1024 columns.
__global__ void __launch_bounds__(256) round4p(const float* __restrict__ in,
                                               float* __restrict__ out) {
    int rowo = blockIdx.x;
    int c4   = threadIdx.x * 4;
    int rowi = (rowo & ~63) | p64(rowo & 63);
    float4 v = *(const float4*)(in + (size_t)rowi * DMODEL + c4);
    *(float4*)(out + (size_t)rowo * DMODEL + c4) =
        make_float4(f2tf(v.x), f2tf(v.y), f2tf(v.z), f2tf(v.w));
}

// ---------------------------------------------------------------------------
// V transpose: vT[h][d][t0 + t'] = v[t0 + p64(t')][h*64 + d]
// grid (S/64, H), 256 threads, smem tile 64x68. Both gmem sides coalesced.
// ---------------------------------------------------------------------------
__global__ void __launch_bounds__(256) vtrans(const float* __restrict__ v,
                                              float* __restrict__ vT) {
    __shared__ float ts[64][68];
    const int t0 = blockIdx.x * 64;
    const int h  = blockIdx.y;
    const int tid = threadIdx.x;

    // load 64t x 64d tile (rows coalesced)
#pragma unroll
    for (int pg = 0; pg < 4; pg++) {
        int t  = pg * 16 + (tid >> 4);
        int c4 = (tid & 15) * 4;
        float4 x4 = *(const float4*)(v + (size_t)(t0 + t) * DMODEL + h * DK + c4);
        *(float4*)&ts[t][c4] = x4;
    }
    __syncthreads();

    // write transposed + t-permuted (rows coalesced)
#pragma unroll
    for (int pg = 0; pg < 4; pg++) {
        int d  = pg * 16 + (tid >> 4);
        int c4 = (tid & 15) * 4;
        float4 o4 = make_float4(ts[p64(c4 + 0)][d], ts[p64(c4 + 1)][d],
                                ts[p64(c4 + 2)][d], ts[p64(c4 + 3)][d]);
        *(float4*)(vT + ((size_t)(h * DK + d)) * S_LEN + t0 + c4) = o4;
    }
}

// ---------------------------------------------------------------------------
// NT GEMM, cp.async double-buffered (unchanged R5/R6 winner)
// ---------------------------------------------------------------------------
#define GBM 128
#define GBN 128
#define GBK 32
#define GLD 36
#define GBUF (GBM * GLD)
#define GB_OFF (2 * GBUF)

template <bool ROUNDC>
__global__ void __launch_bounds__(256) gemm_nt_async(const float* __restrict__ A,
                                                     const float* __restrict__ B,
                                                     float* __restrict__ C,
                                                     int M, int N, int K) {
    extern __shared__ __align__(16) float sm[];
    const uint32_t sb = (uint32_t)__cvta_generic_to_shared(sm);

    const int tid  = threadIdx.x;
    const int warp = tid >> 5, lane = tid & 31;
    const int wm   = warp >> 2;
    const int wn   = warp & 3;
    const int g    = lane >> 2;
    const int tg   = lane & 3;
    const int bm   = blockIdx.y * GBM;
    const int bn   = blockIdx.x * GBN;

    const int lr  = tid >> 3;
    const int lc  = (tid & 7) * 4;

    auto issue = [&](int k0, int buf) {
#pragma unroll
        for (int p = 0; p < 4; p++) {
            int r = lr + p * 32;
            cpa16(sb + (buf * GBUF + r * GLD + lc) * 4,
                  A + (size_t)(bm + r) * K + k0 + lc);
            cpa16(sb + (GB_OFF + buf * GBUF + r * GLD + lc) * 4,
                  B + (size_t)(bn + r) * K + k0 + lc);
        }
        CPA_COMMIT();
    };

    float acc[4][4][4];
#pragma unroll
    for (int mt = 0; mt < 4; mt++)
#pragma unroll
        for (int nt = 0; nt < 4; nt++)
#pragma unroll
            for (int i = 0; i < 4; i++) acc[mt][nt][i] = 0.f;

    issue(0, 0);
    int buf = 0;

    for (int k0 = 0; k0 < K; k0 += GBK) {
        CPA_WAIT0();
        __syncthreads();
        if (k0 + GBK < K) issue(k0 + GBK, buf ^ 1);

        const float* As = sm + buf * GBUF;
        const float* Bs = sm + GB_OFF + buf * GBUF;

#pragma unroll
        for (int ks = 0; ks < GBK / 8; ks++) {
            const int kb = ks * 8;
            uint32_t af[4][4], bf[4][2];
#pragma unroll
            for (int mt = 0; mt < 4; mt++) {
                int r = wm * 64 + mt * 16 + g;
                af[mt][0] = __float_as_uint(As[r * GLD + kb + tg]);
                af[mt][1] = __float_as_uint(As[(r + 8) * GLD + kb + tg]);
                af[mt][2] = __float_as_uint(As[r * GLD + kb + tg + 4]);
                af[mt][3] = __float_as_uint(As[(r + 8) * GLD + kb + tg + 4]);
            }
#pragma unroll
            for (int nt = 0; nt < 4; nt++) {
                int c = wn * 32 + nt * 8 + g;
                bf[nt][0] = __float_as_uint(Bs[c * GLD + kb + tg]);
                bf[nt][1] = __float_as_uint(Bs[c * GLD + kb + tg + 4]);
            }
#pragma unroll
            for (int mt = 0; mt < 4; mt++)
#pragma unroll
                for (int nt = 0; nt < 4; nt++) mma8(acc[mt][nt], af[mt], bf[nt]);
        }
        buf ^= 1;
    }

#pragma unroll
    for (int mt = 0; mt < 4; mt++)
#pragma unroll
        for (int nt = 0; nt < 4; nt++) {
            int r0 = bm + wm * 64 + mt * 16 + g;
            int c  = bn + wn * 32 + nt * 8 + 2 * tg;
            float v0 = acc[mt][nt][0], v1 = acc[mt][nt][1];
            float v2 = acc[mt][nt][2], v3 = acc[mt][nt][3];
            if (ROUNDC) { v0 = f2tf(v0); v1 = f2tf(v1); v2 = f2tf(v2); v3 = f2tf(v3); }
            *(float2*)(C + (size_t)r0 * N + c)       = make_float2(v0, v1);
            *(float2*)(C + (size_t)(r0 + 8) * N + c) = make_float2(v2, v3);
        }
}

// ---------------------------------------------------------------------------
// Flash attention v4: warp-owns-rows + producer-permuted layouts.
// q,k have d-permuted head blocks (via Wq/Wk row perm) -> S-phase K b-frags
// are contiguous 8-float runs (LDS.128). vT is per-head transposed with
// t-permuted tiles -> PV-phase V b-frags contiguous (LDS.128).
// ---------------------------------------------------------------------------
#define BQ 128
#define BT 64
#define KLD 68
#define VTLD 68
#define PLD 68
#define KBUF (BT * KLD)                 // 4352 floats per K buffer
#define VS_OFF (2 * KBUF)               // 8704
#define VBUF (DK * VTLD)                // 4352 (rows d=64, cols t=64+pad)
#define PS_OFF (VS_OFF + 2 * VBUF)      // 17408
#define PWARP (16 * PLD)                // 1088 floats per warp
#define ATTN_SMEM ((PS_OFF + 8 * PWARP) * 4)   // 104448 bytes

__global__ void __launch_bounds__(256, 2) attn_mma(const float* __restrict__ Qg,
                                                   const float* __restrict__ Kg,
                                                   const float* __restrict__ VTg,
                                                   float* __restrict__ Og) {
    extern __shared__ __align__(16) float smf[];
    const uint32_t sb = (uint32_t)__cvta_generic_to_shared(smf);

    const int h   = blockIdx.y;
    const int q0  = blockIdx.x * BQ;
    const int tid = threadIdx.x;
    const int warp = tid >> 5, lane = tid & 31;
    const int g   = lane >> 2;         // 0..7
    const int tg  = lane & 3;          // 0..3
    const int hoff = h * DK;

    const int r0 = warp * 16 + g;
    const int r1 = r0 + 8;

    float* Pw = smf + PS_OFF + warp * PWARP;   // warp-private P [16][PLD]

    const int ld_t  = tid >> 4;        // +16 per p
    const int ld_c4 = (tid & 15) * 4;

    auto issue_kv = [&](int t0, int buf) {
#pragma unroll
        for (int p = 0; p < 4; p++) {
            int t = ld_t + p * 16;     // K: row t (kv idx); V: row d
            const float* kp = Kg + (size_t)(t0 + t) * DMODEL + hoff + ld_c4;
            const float* vp = VTg + (size_t)(hoff + t) * S_LEN + t0 + ld_c4;
            cpa16(sb + (buf * KBUF + t * KLD + ld_c4) * 4, kp);
            cpa16(sb + (VS_OFF + buf * VBUF + t * VTLD + ld_c4) * 4, vp);
        }
        CPA_COMMIT();
    };

    issue_kv(0, 0);

    // ---- Persistent Q fragments (q is d-permuted: logical k at pos p64(k)) ----
    uint32_t qf[8][4];
    {
        const float* qp0 = Qg + (size_t)(q0 + r0) * DMODEL + hoff;
        const float* qp1 = Qg + (size_t)(q0 + r1) * DMODEL + hoff;
#pragma unroll
        for (int ks = 0; ks < 8; ks++) {
            // logical k = 8ks+tg  -> stored at tg*8+ks ; k+4 -> (tg+4)*8+ks
            qf[ks][0] = __float_as_uint(qp0[tg * 8 + ks]       * 0.125f);
            qf[ks][1] = __float_as_uint(qp1[tg * 8 + ks]       * 0.125f);
            qf[ks][2] = __float_as_uint(qp0[(tg + 4) * 8 + ks] * 0.125f);
            qf[ks][3] = __float_as_uint(qp1[(tg + 4) * 8 + ks] * 0.125f);
        }
    }

    float m0 = -1e30f, m1 = -1e30f, l0 = 0.f, l1 = 0.f;
    float oacc[8][4];
#pragma unroll
    for (int nt = 0; nt < 8; nt++)
#pragma unroll
        for (int i = 0; i < 4; i++) oacc[nt][i] = 0.f;

    int buf = 0;
    for (int t0 = 0; t0 < S_LEN; t0 += BT) {
        CPA_WAIT0();
        __syncthreads();   // tile ready AND all warps done with this buffer
        if (t0 + BT < S_LEN) issue_kv(t0 + BT, buf ^ 1);

        const float* Ks = smf + buf * KBUF;           // [t][d-permuted]
        const float* Vt = smf + VS_OFF + buf * VBUF;  // [d][t-permuted]

        // ---- S = (Q/8) K^T : b-frags via 4x LDS.128 per nt ----
        float accS[8][4];
#pragma unroll
        for (int nt = 0; nt < 8; nt++) {
            const int t = nt * 8 + g;
            float bv0[8], bv1[8];
            *(float4*)&bv0[0] = *(const float4*)&Ks[t * KLD + tg * 8];
            *(float4*)&bv0[4] = *(const float4*)&Ks[t * KLD + tg * 8 + 4];
            *(float4*)&bv1[0] = *(const float4*)&Ks[t * KLD + (tg + 4) * 8];
            *(float4*)&bv1[4] = *(const float4*)&Ks[t * KLD + (tg + 4) * 8 + 4];
            accS[nt][0] = accS[nt][1] = accS[nt][2] = accS[nt][3] = 0.f;
#pragma unroll
            for (int ks = 0; ks < 8; ks++) {
                uint32_t b[2] = { __float_as_uint(bv0[ks]), __float_as_uint(bv1[ks]) };
                mma8(accS[nt], qf[ks], b);
            }
        }

        // ---- softmax: rows fully in-warp ----
        float mx0 = -1e30f, mx1 = -1e30f;
#pragma unroll
        for (int nt = 0; nt < 8; nt++) {
            mx0 = fmaxf(mx0, fmaxf(accS[nt][0], accS[nt][1]));
            mx1 = fmaxf(mx1, fmaxf(accS[nt][2], accS[nt][3]));
        }
        mx0 = fmaxf(mx0, __shfl_xor_sync(0xffffffffu, mx0, 1));
        mx0 = fmaxf(mx0, __shfl_xor_sync(0xffffffffu, mx0, 2));
        mx1 = fmaxf(mx1, __shfl_xor_sync(0xffffffffu, mx1, 1));
        mx1 = fmaxf(mx1, __shfl_xor_sync(0xffffffffu, mx1, 2));

        float mn0 = fmaxf(m0, mx0), mn1 = fmaxf(m1, mx1);
        float c0 = __expf(m0 - mn0), c1 = __expf(m1 - mn1);
        m0 = mn0; m1 = mn1;

        float ps0 = 0.f, ps1 = 0.f;
#pragma unroll
        for (int nt = 0; nt < 8; nt++) {
            int c = nt * 8 + 2 * tg;
            float p00 = __expf(accS[nt][0] - m0);
            float p01 = __expf(accS[nt][1] - m0);
            float p10 = __expf(accS[nt][2] - m1);
            float p11 = __expf(accS[nt][3] - m1);
            ps0 += p00 + p01; ps1 += p10 + p11;
            *(float2*)&Pw[g * PLD + c]       = make_float2(f2tf(p00), f2tf(p01));
            *(float2*)&Pw[(g + 8) * PLD + c] = make_float2(f2tf(p10), f2tf(p11));
        }
        ps0 += __shfl_xor_sync(0xffffffffu, ps0, 1);
        ps0 += __shfl_xor_sync(0xffffffffu, ps0, 2);
        ps1 += __shfl_xor_sync(0xffffffffu, ps1, 1);
        ps1 += __shfl_xor_sync(0xffffffffu, ps1, 2);

        l0 = l0 * c0 + ps0;
        l1 = l1 * c1 + ps1;
#pragma unroll
        for (int nt = 0; nt < 8; nt++) {
            oacc[nt][0] *= c0; oacc[nt][1] *= c0;
            oacc[nt][2] *= c1; oacc[nt][3] *= c1;
        }
        __syncwarp();      // P visible within warp

        // ---- O += P V : a-frags cached (32 scalar), V b-frags via LDS.128 ----
        uint32_t af[8][4];
#pragma unroll
        for (int ks = 0; ks < 8; ks++) {
            const int kb = ks * 8;
            af[ks][0] = __float_as_uint(Pw[g * PLD + kb + tg]);
            af[ks][1] = __float_as_uint(Pw[(g + 8) * PLD + kb + tg]);
            af[ks][2] = __float_as_uint(Pw[g * PLD + kb + tg + 4]);
            af[ks][3] = __float_as_uint(Pw[(g + 8) * PLD + kb + tg + 4]);
        }
#pragma unroll
        for (int nt = 0; nt < 8; nt++) {
            const int d = nt * 8 + g;
            float bv0[8], bv1[8];
            // logical t = 8ks+tg stored at col tg*8+ks ; t+4 at (tg+4)*8+ks
            *(float4*)&bv0[0] = *(const float4*)&Vt[d * VTLD + tg * 8];
            *(float4*)&bv0[4] = *(const float4*)&Vt[d * VTLD + tg * 8 + 4];
            *(float4*)&bv1[0] = *(const float4*)&Vt[d * VTLD + (tg + 4) * 8];
            *(float4*)&bv1[4] = *(const float4*)&Vt[d * VTLD + (tg + 4) * 8 + 4];
#pragma unroll
            for (int ks = 0; ks < 8; ks++) {
                uint32_t b[2] = { __float_as_uint(bv0[ks]), __float_as_uint(bv1[ks]) };
                mma8(oacc[nt], af[ks], b);
            }
        }
        __syncwarp();      // P reads done before next-tile writes
        buf ^= 1;
    }

    // ---- normalize + write (natural d layout; rounded for final GEMM) ----
    float inv0 = 1.f / l0, inv1 = 1.f / l1;
#pragma unroll
    for (int nt = 0; nt < 8; nt++) {
        int c = hoff + nt * 8 + 2 * tg;
        *(float2*)(Og + (size_t)(q0 + r0) * DMODEL + c) =
            make_float2(f2tf(oacc[nt][0] * inv0), f2tf(oacc[nt][1] * inv0));
        *(float2*)(Og + (size_t)(q0 + r1) * DMODEL + c) =
            make_float2(f2tf(oacc[nt][2] * inv1), f2tf(oacc[nt][3] * inv1));
    }
}

// ---------------------------------------------------------------------------
extern "C" void kernel_launch(void* const* d_in, const int* in_sizes, int n_in,
                              void* d_out, int out_size) {
    const float* x  = (const float*)d_in[0];
    const float* Wq = (const float*)d_in[1];
    const float* Wk = (const float*)d_in[2];
    const float* Wv = (const float*)d_in[3];
    const float* Wo = (const float*)d_in[4];
    float* out = (float*)d_out;

    float *q, *k, *v, *vT, *ao, *xr, *wr;
    cudaGetSymbolAddress((void**)&q,  g_q);
    cudaGetSymbolAddress((void**)&k,  g_k);
    cudaGetSymbolAddress((void**)&v,  g_v);
    cudaGetSymbolAddress((void**)&vT, g_vT);
    cudaGetSymbolAddress((void**)&ao, g_ao);
    cudaGetSymbolAddress((void**)&xr, g_xr);
    cudaGetSymbolAddress((void**)&wr, g_wr);
    float* wqr = wr;
    float* wkr = wr + (size_t)DMODEL * DMODEL;
    float* wvr = wr + (size_t)2 * DMODEL * DMODEL;
    float* wor = wr + (size_t)3 * DMODEL * DMODEL;

    const int GSM = 4 * GBM * GLD * sizeof(float);   // 73728
    cudaFuncSetAttribute(gemm_nt_async<true>,
                         cudaFuncAttributeMaxDynamicSharedMemorySize, GSM);
    cudaFuncSetAttribute(gemm_nt_async<false>,
                         cudaFuncAttributeMaxDynamicSharedMemorySize, GSM);
    cudaFuncSetAttribute(attn_mma,
                         cudaFuncAttributeMaxDynamicSharedMemorySize, ATTN_SMEM);

    // tf32-round inputs once; Wq/Wk row-permuted so q/k come out d-permuted
    round4 <<<(S_LEN * DMODEL / 4 + 255) / 256, 256>>>(x,  xr,  S_LEN * DMODEL / 4);
    round4p<<<DMODEL, 256>>>(Wq, wqr);
    round4p<<<DMODEL, 256>>>(Wk, wkr);
    round4 <<<(DMODEL * DMODEL / 4 + 255) / 256, 256>>>(Wv, wvr, DMODEL * DMODEL / 4);
    round4 <<<(DMODEL * DMODEL / 4 + 255) / 256, 256>>>(Wo, wor, DMODEL * DMODEL / 4);

    dim3 gg(DMODEL / GBN, S_LEN / GBM);  // (8, 32)
    gemm_nt_async<true><<<gg, 256, GSM>>>(xr, wqr, q, S_LEN, DMODEL, DMODEL);
    gemm_nt_async<true><<<gg, 256, GSM>>>(xr, wkr, k, S_LEN, DMODEL, DMODEL);
    gemm_nt_async<true><<<gg, 256, GSM>>>(xr, wvr, v, S_LEN, DMODEL, DMODEL);

    vtrans<<<dim3(S_LEN / 64, NHEADS), 256>>>(v, vT);

    attn_mma<<<dim3(S_LEN / BQ, NHEADS), 256, ATTN_SMEM>>>(q, k, vT, ao);

    gemm_nt_async<false><<<gg, 256, GSM>>>(ao, wor, out, S_LEN, DMODEL, DMODEL);
}

// round 10
// speedup vs baseline: 1.7989x; 1.7989x over previous
#include <cuda_runtime.h>
#include <cuda_fp16.h>
#include <cstdint>

#define S_LEN   4096
#define DMODEL  1024
#define NHEADS  16
#define DK      64

// Scratch (allocation-free rule: __device__ globals)
__device__ __half g_q [S_LEN * DMODEL];
__device__ __half g_k [S_LEN * DMODEL];
__device__ __half g_v [S_LEN * DMODEL];
__device__ __half g_vT[S_LEN * DMODEL];         // per-head transposed V (half)
__device__ __half g_ao[S_LEN * DMODEL];
__device__ __half g_xr[S_LEN * DMODEL];         // fp16 x
__device__ __half g_wr[4][DMODEL * DMODEL];     // fp16 Wq(*0.125),Wk,Wv,Wo

// ---------------------------------------------------------------------------
// helpers
// ---------------------------------------------------------------------------
__device__ __forceinline__ void mma16(float* d, const uint32_t* a, const uint32_t* b) {
    asm volatile(
        "mma.sync.aligned.m16n8k16.row.col.f32.f16.f16.f32 "
        "{%0,%1,%2,%3}, {%4,%5,%6,%7}, {%8,%9}, {%0,%1,%2,%3};"
        : "+f"(d[0]), "+f"(d[1]), "+f"(d[2]), "+f"(d[3])
        : "r"(a[0]), "r"(a[1]), "r"(a[2]), "r"(a[3]), "r"(b[0]), "r"(b[1]));
}

__device__ __forceinline__ void cpa16(uint32_t dst, const void* src) {
    asm volatile("cp.async.cg.shared.global [%0], [%1], 16;" :: "r"(dst), "l"(src));
}
#define CPA_COMMIT() asm volatile("cp.async.commit_group;")
#define CPA_WAIT0()  asm volatile("cp.async.wait_group 0;" ::: "memory")

// ---------------------------------------------------------------------------
// fp16 rounding pass (optional scale folded in)
// ---------------------------------------------------------------------------
__global__ void __launch_bounds__(256) round4h(const float* __restrict__ in,
                                               __half* __restrict__ out,
                                               int n4, float scale) {
    int i = blockIdx.x * blockDim.x + threadIdx.x;
    if (i < n4) {
        float4 v = ((const float4*)in)[i];
        __half2* o = (__half2*)out + i * 2;
        o[0] = __floats2half2_rn(v.x * scale, v.y * scale);
        o[1] = __floats2half2_rn(v.z * scale, v.w * scale);
    }
}

// ---------------------------------------------------------------------------
// V transpose per head: vT[h*64+d][t] = v[t][h*64+d]   (half)
// ---------------------------------------------------------------------------
__global__ void __launch_bounds__(256) vtrans(const __half* __restrict__ v,
                                              __half* __restrict__ vT) {
    __shared__ __half ts[64][72];
    const int t0 = blockIdx.x * 64;
    const int h  = blockIdx.y;
    const int tid = threadIdx.x;

#pragma unroll
    for (int p = 0; p < 2; p++) {
        int idx = p * 256 + tid;
        int t = idx >> 3, c16 = idx & 7;
        *(float4*)&ts[t][c16 * 8] =
            *(const float4*)(v + (size_t)(t0 + t) * DMODEL + h * DK + c16 * 8);
    }
    __syncthreads();
#pragma unroll
    for (int p = 0; p < 2; p++) {
        int idx = p * 256 + tid;
        int d = idx >> 3, c16 = idx & 7;
        __half tmp[8];
#pragma unroll
        for (int j = 0; j < 8; j++) tmp[j] = ts[c16 * 8 + j][d];
        *(float4*)(vT + (size_t)(h * DK + d) * S_LEN + t0 + c16 * 8) = *(const float4*)tmp;
    }
}

// ---------------------------------------------------------------------------
// NT GEMM fp16 (m16n8k16): C[M,N] = A[M,K] * B[N,K]^T, fp32 accum.
// Block 128x128x32, 8 warps 2(m)x4(n), warp tile 64x32, cp.async dbl-buffered.
// Smem rows padded to 40 halfs -> all frag LDS.32 conflict-free.
// ---------------------------------------------------------------------------
#define GBM 128
#define GBN 128
#define GBK 32
#define GLDH 40
#define GBUFH (GBM * GLDH)          // 5120 halfs per buffer
#define GSMH (4 * GBUFH * 2)        // 40960 bytes total

template <bool OUTH>
__global__ void __launch_bounds__(256) gemm_h(const __half* __restrict__ A,
                                              const __half* __restrict__ B,
                                              void* __restrict__ Cv,
                                              int M, int N, int K) {
    extern __shared__ __align__(16) __half smh[];
    const uint32_t sb = (uint32_t)__cvta_generic_to_shared(smh);

    const int tid  = threadIdx.x;
    const int warp = tid >> 5, lane = tid & 31;
    const int wm   = warp >> 2;
    const int wn   = warp & 3;
    const int g    = lane >> 2;
    const int tg   = lane & 3;
    const int bm   = blockIdx.y * GBM;
    const int bn   = blockIdx.x * GBN;

    auto issue = [&](int k0, int buf) {
#pragma unroll
        for (int p = 0; p < 2; p++) {
            int idx = p * 256 + tid;
            int r = idx >> 2, c16 = idx & 3;       // 128 rows x 4 x 16B (=32 halfs)
            cpa16(sb + (buf * GBUFH + r * GLDH + c16 * 8) * 2,
                  A + (size_t)(bm + r) * K + k0 + c16 * 8);
            cpa16(sb + ((2 * GBUFH + buf * GBUFH) + r * GLDH + c16 * 8) * 2,
                  B + (size_t)(bn + r) * K + k0 + c16 * 8);
        }
        CPA_COMMIT();
    };

    float acc[4][4][4];
#pragma unroll
    for (int mt = 0; mt < 4; mt++)
#pragma unroll
        for (int nt = 0; nt < 4; nt++)
#pragma unroll
            for (int i = 0; i < 4; i++) acc[mt][nt][i] = 0.f;

    issue(0, 0);
    int buf = 0;

    for (int k0 = 0; k0 < K; k0 += GBK) {
        CPA_WAIT0();
        __syncthreads();
        if (k0 + GBK < K) issue(k0 + GBK, buf ^ 1);

        const uint32_t* Au = (const uint32_t*)(smh + buf * GBUFH);
        const uint32_t* Bu = (const uint32_t*)(smh + 2 * GBUFH + buf * GBUFH);

#pragma unroll
        for (int ks = 0; ks < 2; ks++) {            // k16 steps
            const int kb = ks * 8;                  // u32 offset
            uint32_t af[4][4], bf[4][2];
#pragma unroll
            for (int mt = 0; mt < 4; mt++) {
                int r = wm * 64 + mt * 16 + g;
                af[mt][0] = Au[r * 20 + kb + tg];
                af[mt][1] = Au[(r + 8) * 20 + kb + tg];
                af[mt][2] = Au[r * 20 + kb + tg + 4];
                af[mt][3] = Au[(r + 8) * 20 + kb + tg + 4];
            }
#pragma unroll
            for (int nt = 0; nt < 4; nt++) {
                int c = wn * 32 + nt * 8 + g;
                bf[nt][0] = Bu[c * 20 + kb + tg];
                bf[nt][1] = Bu[c * 20 + kb + tg + 4];
            }
#pragma unroll
            for (int mt = 0; mt < 4; mt++)
#pragma unroll
                for (int nt = 0; nt < 4; nt++) mma16(acc[mt][nt], af[mt], bf[nt]);
        }
        buf ^= 1;
    }

#pragma unroll
    for (int mt = 0; mt < 4; mt++)
#pragma unroll
        for (int nt = 0; nt < 4; nt++) {
            int r0 = bm + wm * 64 + mt * 16 + g;
            int c  = bn + wn * 32 + nt * 8 + 2 * tg;
            if (OUTH) {
                __half* C = (__half*)Cv;
                *(__half2*)(C + (size_t)r0 * N + c) =
                    __floats2half2_rn(acc[mt][nt][0], acc[mt][nt][1]);
                *(__half2*)(C + (size_t)(r0 + 8) * N + c) =
                    __floats2half2_rn(acc[mt][nt][2], acc[mt][nt][3]);
            } else {
                float* C = (float*)Cv;
                *(float2*)(C + (size_t)r0 * N + c)       = make_float2(acc[mt][nt][0], acc[mt][nt][1]);
                *(float2*)(C + (size_t)(r0 + 8) * N + c) = make_float2(acc[mt][nt][2], acc[mt][nt][3]);
            }
        }
}

// ---------------------------------------------------------------------------
// Flash attention fp16 (m16n8k16), warp-owns-rows (R7 structure).
// Smem (halfs): K[2][64][72], Vt[2][64][72] (per-head V^T), P[8 warps][16][72].
// Q pre-scaled by 1/8 via Wq. fp32 softmax/accum.
// ---------------------------------------------------------------------------
#define BQ 128
#define BT 64
#define LDH 72                          // halfs per row everywhere
#define KBUF_H (BT * LDH)               // 4608
#define VS_OFF_H (2 * KBUF_H)           // 9216
#define PS_OFF_H (VS_OFF_H + 2 * KBUF_H)// 18432
#define PWARP_H (16 * LDH)              // 1152
#define ATTN_SMEM ((PS_OFF_H + 8 * PWARP_H) * 2)   // 55296 bytes

__global__ void __launch_bounds__(256, 2) attn_mma(const __half* __restrict__ Qg,
                                                   const __half* __restrict__ Kg,
                                                   const __half* __restrict__ VTg,
                                                   __half* __restrict__ Og) {
    extern __shared__ __align__(16) __half smh[];
    const uint32_t sb = (uint32_t)__cvta_generic_to_shared(smh);

    const int h   = blockIdx.y;
    const int q0  = blockIdx.x * BQ;
    const int tid = threadIdx.x;
    const int warp = tid >> 5, lane = tid & 31;
    const int g   = lane >> 2;
    const int tg  = lane & 3;
    const int hoff = h * DK;

    const int r0 = warp * 16 + g;
    const int r1 = r0 + 8;

    uint32_t* Pu = (uint32_t*)(smh + PS_OFF_H + warp * PWARP_H);  // [16][36] u32

    auto issue_kv = [&](int t0, int buf) {
#pragma unroll
        for (int p = 0; p < 2; p++) {
            int idx = p * 256 + tid;
            int r = idx >> 3, c16 = idx & 7;        // 64 rows x 8 x 16B (=64 halfs)
            cpa16(sb + (buf * KBUF_H + r * LDH + c16 * 8) * 2,
                  Kg + (size_t)(t0 + r) * DMODEL + hoff + c16 * 8);
            cpa16(sb + ((VS_OFF_H + buf * KBUF_H) + r * LDH + c16 * 8) * 2,
                  VTg + (size_t)(hoff + r) * S_LEN + t0 + c16 * 8);
        }
        CPA_COMMIT();
    };

    issue_kv(0, 0);

    // ---- Persistent Q fragments (pre-scaled; u32 = half pair) ----
    uint32_t qf[4][4];
    {
        const uint32_t* qu0 = (const uint32_t*)(Qg + (size_t)(q0 + r0) * DMODEL + hoff);
        const uint32_t* qu1 = (const uint32_t*)(Qg + (size_t)(q0 + r1) * DMODEL + hoff);
#pragma unroll
        for (int ks = 0; ks < 4; ks++) {
            qf[ks][0] = qu0[ks * 8 + tg];
            qf[ks][1] = qu1[ks * 8 + tg];
            qf[ks][2] = qu0[ks * 8 + tg + 4];
            qf[ks][3] = qu1[ks * 8 + tg + 4];
        }
    }

    float m0 = -1e30f, m1 = -1e30f, l0 = 0.f, l1 = 0.f;
    float oacc[8][4];
#pragma unroll
    for (int nt = 0; nt < 8; nt++)
#pragma unroll
        for (int i = 0; i < 4; i++) oacc[nt][i] = 0.f;

    int buf = 0;
    for (int t0 = 0; t0 < S_LEN; t0 += BT) {
        CPA_WAIT0();
        __syncthreads();
        if (t0 + BT < S_LEN) issue_kv(t0 + BT, buf ^ 1);

        const uint32_t* Ku = (const uint32_t*)(smh + buf * KBUF_H);            // [t][36]
        const uint32_t* Vu = (const uint32_t*)(smh + VS_OFF_H + buf * KBUF_H); // [d][36]

        // ---- S = Qs K^T : 4 k16-steps x 8 nt ----
        float accS[8][4];
#pragma unroll
        for (int nt = 0; nt < 8; nt++)
#pragma unroll
            for (int i = 0; i < 4; i++) accS[nt][i] = 0.f;

#pragma unroll
        for (int ks = 0; ks < 4; ks++) {
            const int kb = ks * 8;
#pragma unroll
            for (int nt = 0; nt < 8; nt++) {
                int t = nt * 8 + g;
                uint32_t b[2] = { Ku[t * 36 + kb + tg], Ku[t * 36 + kb + tg + 4] };
                mma16(accS[nt], qf[ks], b);
            }
        }

        // ---- softmax: rows fully in-warp ----
        float mx0 = -1e30f, mx1 = -1e30f;
#pragma unroll
        for (int nt = 0; nt < 8; nt++) {
            mx0 = fmaxf(mx0, fmaxf(accS[nt][0], accS[nt][1]));
            mx1 = fmaxf(mx1, fmaxf(accS[nt][2], accS[nt][3]));
        }
        mx0 = fmaxf(mx0, __shfl_xor_sync(0xffffffffu, mx0, 1));
        mx0 = fmaxf(mx0, __shfl_xor_sync(0xffffffffu, mx0, 2));
        mx1 = fmaxf(mx1, __shfl_xor_sync(0xffffffffu, mx1, 1));
        mx1 = fmaxf(mx1, __shfl_xor_sync(0xffffffffu, mx1, 2));

        float mn0 = fmaxf(m0, mx0), mn1 = fmaxf(m1, mx1);
        float c0 = __expf(m0 - mn0), c1 = __expf(m1 - mn1);
        m0 = mn0; m1 = mn1;

        float ps0 = 0.f, ps1 = 0.f;
#pragma unroll
        for (int nt = 0; nt < 8; nt++) {
            float p00 = __expf(accS[nt][0] - m0);
            float p01 = __expf(accS[nt][1] - m0);
            float p10 = __expf(accS[nt][2] - m1);
            float p11 = __expf(accS[nt][3] - m1);
            ps0 += p00 + p01; ps1 += p10 + p11;
            __half2 h0 = __floats2half2_rn(p00, p01);
            __half2 h1 = __floats2half2_rn(p10, p11);
            Pu[g * 36 + nt * 4 + tg]       = *(uint32_t*)&h0;   // row g, cols nt*8+2tg
            Pu[(g + 8) * 36 + nt * 4 + tg] = *(uint32_t*)&h1;   // row g+8
        }
        ps0 += __shfl_xor_sync(0xffffffffu, ps0, 1);
        ps0 += __shfl_xor_sync(0xffffffffu, ps0, 2);
        ps1 += __shfl_xor_sync(0xffffffffu, ps1, 1);
        ps1 += __shfl_xor_sync(0xffffffffu, ps1, 2);

        l0 = l0 * c0 + ps0;
        l1 = l1 * c1 + ps1;
#pragma unroll
        for (int nt = 0; nt < 8; nt++) {
            oacc[nt][0] *= c0; oacc[nt][1] *= c0;
            oacc[nt][2] *= c1; oacc[nt][3] *= c1;
        }
        __syncwarp();      // P visible within warp

        // ---- O += P V : A=P[16][64], B=V^T[d][t] ----
#pragma unroll
        for (int ks = 0; ks < 4; ks++) {
            const int kb = ks * 8;
            uint32_t af[4];
            af[0] = Pu[g * 36 + kb + tg];
            af[1] = Pu[(g + 8) * 36 + kb + tg];
            af[2] = Pu[g * 36 + kb + tg + 4];
            af[3] = Pu[(g + 8) * 36 + kb + tg + 4];
#pragma unroll
            for (int nt = 0; nt < 8; nt++) {
                int d = nt * 8 + g;
                uint32_t b[2] = { Vu[d * 36 + kb + tg], Vu[d * 36 + kb + tg + 4] };
                mma16(oacc[nt], af, b);
            }
        }
        __syncwarp();      // P reads done before next-tile writes
        buf ^= 1;
    }

    // ---- normalize + write half2 ----
    float inv0 = 1.f / l0, inv1 = 1.f / l1;
#pragma unroll
    for (int nt = 0; nt < 8; nt++) {
        int c = hoff + nt * 8 + 2 * tg;
        *(__half2*)(Og + (size_t)(q0 + r0) * DMODEL + c) =
            __floats2half2_rn(oacc[nt][0] * inv0, oacc[nt][1] * inv0);
        *(__half2*)(Og + (size_t)(q0 + r1) * DMODEL + c) =
            __floats2half2_rn(oacc[nt][2] * inv1, oacc[nt][3] * inv1);
    }
}

// ---------------------------------------------------------------------------
extern "C" void kernel_launch(void* const* d_in, const int* in_sizes, int n_in,
                              void* d_out, int out_size) {
    const float* x  = (const float*)d_in[0];
    const float* Wq = (const float*)d_in[1];
    const float* Wk = (const float*)d_in[2];
    const float* Wv = (const float*)d_in[3];
    const float* Wo = (const float*)d_in[4];
    float* out = (float*)d_out;

    __half *q, *k, *v, *vT, *ao, *xr, *wr;
    cudaGetSymbolAddress((void**)&q,  g_q);
    cudaGetSymbolAddress((void**)&k,  g_k);
    cudaGetSymbolAddress((void**)&v,  g_v);
    cudaGetSymbolAddress((void**)&vT, g_vT);
    cudaGetSymbolAddress((void**)&ao, g_ao);
    cudaGetSymbolAddress((void**)&xr, g_xr);
    cudaGetSymbolAddress((void**)&wr, g_wr);
    __half* wqr = wr;
    __half* wkr = wr + (size_t)DMODEL * DMODEL;
    __half* wvr = wr + (size_t)2 * DMODEL * DMODEL;
    __half* wor = wr + (size_t)3 * DMODEL * DMODEL;

    cudaFuncSetAttribute(gemm_h<true>,
                         cudaFuncAttributeMaxDynamicSharedMemorySize, GSMH);
    cudaFuncSetAttribute(gemm_h<false>,
                         cudaFuncAttributeMaxDynamicSharedMemorySize, GSMH);
    cudaFuncSetAttribute(attn_mma,
                         cudaFuncAttributeMaxDynamicSharedMemorySize, ATTN_SMEM);

    // fp16-round inputs once; 1/sqrt(dk)=0.125 folded into Wq
    round4h<<<(S_LEN * DMODEL / 4 + 255) / 256, 256>>>(x,  xr,  S_LEN * DMODEL / 4, 1.0f);
    round4h<<<(DMODEL * DMODEL / 4 + 255) / 256, 256>>>(Wq, wqr, DMODEL * DMODEL / 4, 0.125f);
    round4h<<<(DMODEL * DMODEL / 4 + 255) / 256, 256>>>(Wk, wkr, DMODEL * DMODEL / 4, 1.0f);
    round4h<<<(DMODEL * DMODEL / 4 + 255) / 256, 256>>>(Wv, wvr, DMODEL * DMODEL / 4, 1.0f);
    round4h<<<(DMODEL * DMODEL / 4 + 255) / 256, 256>>>(Wo, wor, DMODEL * DMODEL / 4, 1.0f);

    dim3 gg(DMODEL / GBN, S_LEN / GBM);  // (8, 32)
    gemm_h<true><<<gg, 256, GSMH>>>(xr, wqr, q, S_LEN, DMODEL, DMODEL);
    gemm_h<true><<<gg, 256, GSMH>>>(xr, wkr, k, S_LEN, DMODEL, DMODEL);
    gemm_h<true><<<gg, 256, GSMH>>>(xr, wvr, v, S_LEN, DMODEL, DMODEL);

    vtrans<<<dim3(S_LEN / 64, NHEADS), 256>>>(v, vT);

    attn_mma<<<dim3(S_LEN / BQ, NHEADS), 256, ATTN_SMEM>>>(q, k, vT, ao);

    gemm_h<false><<<gg, 256, GSMH>>>(ao, wor, out, S_LEN, DMODEL, DMODEL);
}

// round 11
// speedup vs baseline: 1.9476x; 1.0827x over previous
#include <cuda_runtime.h>
#include <cuda_fp16.h>
#include <cstdint>

#define S_LEN   4096
#define DMODEL  1024
#define NHEADS  16
#define DK      64

// Scratch (allocation-free rule: __device__ globals)
__device__ __half g_q [S_LEN * DMODEL];
__device__ __half g_k [S_LEN * DMODEL];
__device__ __half g_v [S_LEN * DMODEL];
__device__ __half g_vT[S_LEN * DMODEL];         // per-head transposed V (half)
__device__ __half g_ao[S_LEN * DMODEL];
__device__ __half g_xr[S_LEN * DMODEL];         // fp16 x
__device__ __half g_wr[4][DMODEL * DMODEL];     // fp16 Wq(*0.125*log2e),Wk,Wv,Wo

#define QSCALE (0.125f * 1.44269504088896340736f)   // 1/sqrt(dk) * log2(e)

// ---------------------------------------------------------------------------
// helpers
// ---------------------------------------------------------------------------
__device__ __forceinline__ void mma16(float* d, const uint32_t* a, const uint32_t* b) {
    asm volatile(
        "mma.sync.aligned.m16n8k16.row.col.f32.f16.f16.f32 "
        "{%0,%1,%2,%3}, {%4,%5,%6,%7}, {%8,%9}, {%0,%1,%2,%3};"
        : "+f"(d[0]), "+f"(d[1]), "+f"(d[2]), "+f"(d[3])
        : "r"(a[0]), "r"(a[1]), "r"(a[2]), "r"(a[3]), "r"(b[0]), "r"(b[1]));
}

__device__ __forceinline__ void cpa16(uint32_t dst, const void* src) {
    asm volatile("cp.async.cg.shared.global [%0], [%1], 16;" :: "r"(dst), "l"(src));
}
#define CPA_COMMIT() asm volatile("cp.async.commit_group;")
#define CPA_WAIT0()  asm volatile("cp.async.wait_group 0;" ::: "memory")

// ---------------------------------------------------------------------------
// fp16 rounding: x (grid.y==0 path handled by separate launch), weights merged
// ---------------------------------------------------------------------------
__global__ void __launch_bounds__(256) round4h(const float* __restrict__ in,
                                               __half* __restrict__ out,
                                               int n4, float scale) {
    int i = blockIdx.x * blockDim.x + threadIdx.x;
    if (i < n4) {
        float4 v = ((const float4*)in)[i];
        __half2* o = (__half2*)out + i * 2;
        o[0] = __floats2half2_rn(v.x * scale, v.y * scale);
        o[1] = __floats2half2_rn(v.z * scale, v.w * scale);
    }
}

// all 4 weights in one launch: blockIdx.y selects the matrix
__global__ void __launch_bounds__(256) round4w(const float* __restrict__ w0,
                                               const float* __restrict__ w1,
                                               const float* __restrict__ w2,
                                               const float* __restrict__ w3,
                                               __half* __restrict__ out) {
    const float* src[4] = { w0, w1, w2, w3 };
    const float scl[4]  = { QSCALE, 1.f, 1.f, 1.f };
    int m = blockIdx.y;
    int i = blockIdx.x * blockDim.x + threadIdx.x;   // n4 = D*D/4 = 262144
    float s = scl[m];
    float4 v = ((const float4*)src[m])[i];
    __half2* o = (__half2*)(out + (size_t)m * DMODEL * DMODEL) + i * 2;
    o[0] = __floats2half2_rn(v.x * s, v.y * s);
    o[1] = __floats2half2_rn(v.z * s, v.w * s);
}

// ---------------------------------------------------------------------------
// V transpose per head: vT[h*64+d][t] = v[t][h*64+d]   (half)
// ---------------------------------------------------------------------------
__global__ void __launch_bounds__(256) vtrans(const __half* __restrict__ v,
                                              __half* __restrict__ vT) {
    __shared__ __half ts[64][72];
    const int t0 = blockIdx.x * 64;
    const int h  = blockIdx.y;
    const int tid = threadIdx.x;

#pragma unroll
    for (int p = 0; p < 2; p++) {
        int idx = p * 256 + tid;
        int t = idx >> 3, c16 = idx & 7;
        *(float4*)&ts[t][c16 * 8] =
            *(const float4*)(v + (size_t)(t0 + t) * DMODEL + h * DK + c16 * 8);
    }
    __syncthreads();
#pragma unroll
    for (int p = 0; p < 2; p++) {
        int idx = p * 256 + tid;
        int d = idx >> 3, c16 = idx & 7;
        __half tmp[8];
#pragma unroll
        for (int j = 0; j < 8; j++) tmp[j] = ts[c16 * 8 + j][d];
        *(float4*)(vT + (size_t)(h * DK + d) * S_LEN + t0 + c16 * 8) = *(const float4*)tmp;
    }
}

// ---------------------------------------------------------------------------
// NT GEMM fp16 (m16n8k16)  — unchanged R9 winner
// ---------------------------------------------------------------------------
#define GBM 128
#define GBN 128
#define GBK 32
#define GLDH 40
#define GBUFH (GBM * GLDH)
#define GSMH (4 * GBUFH * 2)

template <bool OUTH>
__global__ void __launch_bounds__(256) gemm_h(const __half* __restrict__ A,
                                              const __half* __restrict__ B,
                                              void* __restrict__ Cv,
                                              int M, int N, int K) {
    extern __shared__ __align__(16) __half smh[];
    const uint32_t sb = (uint32_t)__cvta_generic_to_shared(smh);

    const int tid  = threadIdx.x;
    const int warp = tid >> 5, lane = tid & 31;
    const int wm   = warp >> 2;
    const int wn   = warp & 3;
    const int g    = lane >> 2;
    const int tg   = lane & 3;
    const int bm   = blockIdx.y * GBM;
    const int bn   = blockIdx.x * GBN;

    auto issue = [&](int k0, int buf) {
#pragma unroll
        for (int p = 0; p < 2; p++) {
            int idx = p * 256 + tid;
            int r = idx >> 2, c16 = idx & 3;
            cpa16(sb + (buf * GBUFH + r * GLDH + c16 * 8) * 2,
                  A + (size_t)(bm + r) * K + k0 + c16 * 8);
            cpa16(sb + ((2 * GBUFH + buf * GBUFH) + r * GLDH + c16 * 8) * 2,
                  B + (size_t)(bn + r) * K + k0 + c16 * 8);
        }
        CPA_COMMIT();
    };

    float acc[4][4][4];
#pragma unroll
    for (int mt = 0; mt < 4; mt++)
#pragma unroll
        for (int nt = 0; nt < 4; nt++)
#pragma unroll
            for (int i = 0; i < 4; i++) acc[mt][nt][i] = 0.f;

    issue(0, 0);
    int buf = 0;

    for (int k0 = 0; k0 < K; k0 += GBK) {
        CPA_WAIT0();
        __syncthreads();
        if (k0 + GBK < K) issue(k0 + GBK, buf ^ 1);

        const uint32_t* Au = (const uint32_t*)(smh + buf * GBUFH);
        const uint32_t* Bu = (const uint32_t*)(smh + 2 * GBUFH + buf * GBUFH);

#pragma unroll
        for (int ks = 0; ks < 2; ks++) {
            const int kb = ks * 8;
            uint32_t af[4][4], bf[4][2];
#pragma unroll
            for (int mt = 0; mt < 4; mt++) {
                int r = wm * 64 + mt * 16 + g;
                af[mt][0] = Au[r * 20 + kb + tg];
                af[mt][1] = Au[(r + 8) * 20 + kb + tg];
                af[mt][2] = Au[r * 20 + kb + tg + 4];
                af[mt][3] = Au[(r + 8) * 20 + kb + tg + 4];
            }
#pragma unroll
            for (int nt = 0; nt < 4; nt++) {
                int c = wn * 32 + nt * 8 + g;
                bf[nt][0] = Bu[c * 20 + kb + tg];
                bf[nt][1] = Bu[c * 20 + kb + tg + 4];
            }
#pragma unroll
            for (int mt = 0; mt < 4; mt++)
#pragma unroll
                for (int nt = 0; nt < 4; nt++) mma16(acc[mt][nt], af[mt], bf[nt]);
        }
        buf ^= 1;
    }

#pragma unroll
    for (int mt = 0; mt < 4; mt++)
#pragma unroll
        for (int nt = 0; nt < 4; nt++) {
            int r0 = bm + wm * 64 + mt * 16 + g;
            int c  = bn + wn * 32 + nt * 8 + 2 * tg;
            if (OUTH) {
                __half* C = (__half*)Cv;
                *(__half2*)(C + (size_t)r0 * N + c) =
                    __floats2half2_rn(acc[mt][nt][0], acc[mt][nt][1]);
                *(__half2*)(C + (size_t)(r0 + 8) * N + c) =
                    __floats2half2_rn(acc[mt][nt][2], acc[mt][nt][3]);
            } else {
                float* C = (float*)Cv;
                *(float2*)(C + (size_t)r0 * N + c)       = make_float2(acc[mt][nt][0], acc[mt][nt][1]);
                *(float2*)(C + (size_t)(r0 + 8) * N + c) = make_float2(acc[mt][nt][2], acc[mt][nt][3]);
            }
        }
}

// ---------------------------------------------------------------------------
// Flash attention fp16 v2: P STAYS IN REGISTERS.
// The S C-fragment layout == the PV A-fragment layout, so exp(S) packs
// directly into PV operands. No P smem, no syncwarp. S is computed in
// log2 domain (Wq pre-scaled by 0.125*log2e) -> exp2f (pure MUFU).
// ---------------------------------------------------------------------------
#define BQ 128
#define BT 64
#define LDH 72
#define KBUF_H (BT * LDH)               // 4608 halfs
#define VS_OFF_H (2 * KBUF_H)           // 9216
#define ATTN_SMEM ((VS_OFF_H + 2 * KBUF_H) * 2)   // 36864 bytes

__global__ void __launch_bounds__(256, 2) attn_mma(const __half* __restrict__ Qg,
                                                   const __half* __restrict__ Kg,
                                                   const __half* __restrict__ VTg,
                                                   __half* __restrict__ Og) {
    extern __shared__ __align__(16) __half smh[];
    const uint32_t sb = (uint32_t)__cvta_generic_to_shared(smh);

    const int h   = blockIdx.y;
    const int q0  = blockIdx.x * BQ;
    const int tid = threadIdx.x;
    const int warp = tid >> 5, lane = tid & 31;
    const int g   = lane >> 2;
    const int tg  = lane & 3;
    const int hoff = h * DK;

    const int r0 = warp * 16 + g;
    const int r1 = r0 + 8;

    auto issue_kv = [&](int t0, int buf) {
#pragma unroll
        for (int p = 0; p < 2; p++) {
            int idx = p * 256 + tid;
            int r = idx >> 3, c16 = idx & 7;
            cpa16(sb + (buf * KBUF_H + r * LDH + c16 * 8) * 2,
                  Kg + (size_t)(t0 + r) * DMODEL + hoff + c16 * 8);
            cpa16(sb + ((VS_OFF_H + buf * KBUF_H) + r * LDH + c16 * 8) * 2,
                  VTg + (size_t)(hoff + r) * S_LEN + t0 + c16 * 8);
        }
        CPA_COMMIT();
    };

    issue_kv(0, 0);

    // ---- Persistent Q fragments (pre-scaled by 0.125*log2e via Wq) ----
    uint32_t qf[4][4];
    {
        const uint32_t* qu0 = (const uint32_t*)(Qg + (size_t)(q0 + r0) * DMODEL + hoff);
        const uint32_t* qu1 = (const uint32_t*)(Qg + (size_t)(q0 + r1) * DMODEL + hoff);
#pragma unroll
        for (int ks = 0; ks < 4; ks++) {
            qf[ks][0] = qu0[ks * 8 + tg];
            qf[ks][1] = qu1[ks * 8 + tg];
            qf[ks][2] = qu0[ks * 8 + tg + 4];
            qf[ks][3] = qu1[ks * 8 + tg + 4];
        }
    }

    float m0 = -1e30f, m1 = -1e30f, l0 = 0.f, l1 = 0.f;
    float oacc[8][4];
#pragma unroll
    for (int nt = 0; nt < 8; nt++)
#pragma unroll
        for (int i = 0; i < 4; i++) oacc[nt][i] = 0.f;

    int buf = 0;
    for (int t0 = 0; t0 < S_LEN; t0 += BT) {
        CPA_WAIT0();
        __syncthreads();
        if (t0 + BT < S_LEN) issue_kv(t0 + BT, buf ^ 1);

        const uint32_t* Ku = (const uint32_t*)(smh + buf * KBUF_H);            // [t][36]
        const uint32_t* Vu = (const uint32_t*)(smh + VS_OFF_H + buf * KBUF_H); // [d][36]

        // ---- S' = Qs K^T (log2 domain) ----
        float accS[8][4];
#pragma unroll
        for (int nt = 0; nt < 8; nt++)
#pragma unroll
            for (int i = 0; i < 4; i++) accS[nt][i] = 0.f;

#pragma unroll
        for (int ks = 0; ks < 4; ks++) {
            const int kb = ks * 8;
#pragma unroll
            for (int nt = 0; nt < 8; nt++) {
                int t = nt * 8 + g;
                uint32_t b[2] = { Ku[t * 36 + kb + tg], Ku[t * 36 + kb + tg + 4] };
                mma16(accS[nt], qf[ks], b);
            }
        }

        // ---- softmax (base 2), rows fully in-warp ----
        float mx0 = -1e30f, mx1 = -1e30f;
#pragma unroll
        for (int nt = 0; nt < 8; nt++) {
            mx0 = fmaxf(mx0, fmaxf(accS[nt][0], accS[nt][1]));
            mx1 = fmaxf(mx1, fmaxf(accS[nt][2], accS[nt][3]));
        }
        mx0 = fmaxf(mx0, __shfl_xor_sync(0xffffffffu, mx0, 1));
        mx0 = fmaxf(mx0, __shfl_xor_sync(0xffffffffu, mx0, 2));
        mx1 = fmaxf(mx1, __shfl_xor_sync(0xffffffffu, mx1, 1));
        mx1 = fmaxf(mx1, __shfl_xor_sync(0xffffffffu, mx1, 2));

        float mn0 = fmaxf(m0, mx0), mn1 = fmaxf(m1, mx1);
        float c0 = exp2f(m0 - mn0), c1 = exp2f(m1 - mn1);
        m0 = mn0; m1 = mn1;

        // exp2 -> pack into PV A-fragments IN REGISTERS (C-frag == A-frag layout)
        uint32_t pa0[8], pa1[8];     // pa0: row g, pa1: row g+8, per nt
        float ps0 = 0.f, ps1 = 0.f;
#pragma unroll
        for (int nt = 0; nt < 8; nt++) {
            float p00 = exp2f(accS[nt][0] - m0);
            float p01 = exp2f(accS[nt][1] - m0);
            float p10 = exp2f(accS[nt][2] - m1);
            float p11 = exp2f(accS[nt][3] - m1);
            ps0 += p00 + p01; ps1 += p10 + p11;
            __half2 h0 = __floats2half2_rn(p00, p01);
            __half2 h1 = __floats2half2_rn(p10, p11);
            pa0[nt] = *(uint32_t*)&h0;
            pa1[nt] = *(uint32_t*)&h1;
        }
        ps0 += __shfl_xor_sync(0xffffffffu, ps0, 1);
        ps0 += __shfl_xor_sync(0xffffffffu, ps0, 2);
        ps1 += __shfl_xor_sync(0xffffffffu, ps1, 1);
        ps1 += __shfl_xor_sync(0xffffffffu, ps1, 2);

        l0 = l0 * c0 + ps0;
        l1 = l1 * c1 + ps1;
#pragma unroll
        for (int nt = 0; nt < 8; nt++) {
            oacc[nt][0] *= c0; oacc[nt][1] *= c0;
            oacc[nt][2] *= c1; oacc[nt][3] *= c1;
        }

        // ---- O += P V : A-frags straight from registers ----
#pragma unroll
        for (int ks = 0; ks < 4; ks++) {
            const int kb = ks * 8;
            uint32_t af[4] = { pa0[2 * ks], pa1[2 * ks], pa0[2 * ks + 1], pa1[2 * ks + 1] };
#pragma unroll
            for (int nt = 0; nt < 8; nt++) {
                int d = nt * 8 + g;
                uint32_t b[2] = { Vu[d * 36 + kb + tg], Vu[d * 36 + kb + tg + 4] };
                mma16(oacc[nt], af, b);
            }
        }
        buf ^= 1;
    }

    // ---- normalize + write half2 ----
    float inv0 = 1.f / l0, inv1 = 1.f / l1;
#pragma unroll
    for (int nt = 0; nt < 8; nt++) {
        int c = hoff + nt * 8 + 2 * tg;
        *(__half2*)(Og + (size_t)(q0 + r0) * DMODEL + c) =
            __floats2half2_rn(oacc[nt][0] * inv0, oacc[nt][1] * inv0);
        *(__half2*)(Og + (size_t)(q0 + r1) * DMODEL + c) =
            __floats2half2_rn(oacc[nt][2] * inv1, oacc[nt][3] * inv1);
    }
}

// ---------------------------------------------------------------------------
extern "C" void kernel_launch(void* const* d_in, const int* in_sizes, int n_in,
                              void* d_out, int out_size) {
    const float* x  = (const float*)d_in[0];
    const float* Wq = (const float*)d_in[1];
    const float* Wk = (const float*)d_in[2];
    const float* Wv = (const float*)d_in[3];
    const float* Wo = (const float*)d_in[4];
    float* out = (float*)d_out;

    __half *q, *k, *v, *vT, *ao, *xr, *wr;
    cudaGetSymbolAddress((void**)&q,  g_q);
    cudaGetSymbolAddress((void**)&k,  g_k);
    cudaGetSymbolAddress((void**)&v,  g_v);
    cudaGetSymbolAddress((void**)&vT, g_vT);
    cudaGetSymbolAddress((void**)&ao, g_ao);
    cudaGetSymbolAddress((void**)&xr, g_xr);
    cudaGetSymbolAddress((void**)&wr, g_wr);
    __half* wqr = wr;
    __half* wkr = wr + (size_t)DMODEL * DMODEL;
    __half* wvr = wr + (size_t)2 * DMODEL * DMODEL;
    __half* wor = wr + (size_t)3 * DMODEL * DMODEL;

    cudaFuncSetAttribute(gemm_h<true>,
                         cudaFuncAttributeMaxDynamicSharedMemorySize, GSMH);
    cudaFuncSetAttribute(gemm_h<false>,
                         cudaFuncAttributeMaxDynamicSharedMemorySize, GSMH);
    cudaFuncSetAttribute(attn_mma,
                         cudaFuncAttributeMaxDynamicSharedMemorySize, ATTN_SMEM);

    // fp16-round inputs once; 0.125*log2e folded into Wq (inside round4w)
    round4h<<<(S_LEN * DMODEL / 4 + 255) / 256, 256>>>(x, xr, S_LEN * DMODEL / 4, 1.0f);
    round4w<<<dim3(DMODEL * DMODEL / 4 / 256, 4), 256>>>(Wq, Wk, Wv, Wo, wr);

    dim3 gg(DMODEL / GBN, S_LEN / GBM);  // (8, 32)
    gemm_h<true><<<gg, 256, GSMH>>>(xr, wqr, q, S_LEN, DMODEL, DMODEL);
    gemm_h<true><<<gg, 256, GSMH>>>(xr, wkr, k, S_LEN, DMODEL, DMODEL);
    gemm_h<true><<<gg, 256, GSMH>>>(xr, wvr, v, S_LEN, DMODEL, DMODEL);

    vtrans<<<dim3(S_LEN / 64, NHEADS), 256>>>(v, vT);

    attn_mma<<<dim3(S_LEN / BQ, NHEADS), 256, ATTN_SMEM>>>(q, k, vT, ao);

    gemm_h<false><<<gg, 256, GSMH>>>(ao, wor, out, S_LEN, DMODEL, DMODEL);
}

// round 12
// speedup vs baseline: 2.0107x; 1.0324x over previous
#include <cuda_runtime.h>
#include <cuda_fp16.h>
#include <cstdint>

#define S_LEN   4096
#define DMODEL  1024
#define NHEADS  16
#define DK      64

// Scratch (allocation-free rule: __device__ globals)
__device__ __half g_qkv[3 * S_LEN * DMODEL];    // q | k | v contiguous
__device__ __half g_vT [S_LEN * DMODEL];        // per-head transposed V
__device__ __half g_ao [S_LEN * DMODEL];
__device__ __half g_xr [S_LEN * DMODEL];        // fp16 x
__device__ __half g_wr [4][DMODEL * DMODEL];    // fp16 Wq(*0.125*log2e),Wk,Wv,Wo

#define QSCALE (0.125f * 1.44269504088896340736f)   // 1/sqrt(dk) * log2(e)

// ---------------------------------------------------------------------------
// helpers
// ---------------------------------------------------------------------------
__device__ __forceinline__ void mma16(float* d, const uint32_t* a, const uint32_t* b) {
    asm volatile(
        "mma.sync.aligned.m16n8k16.row.col.f32.f16.f16.f32 "
        "{%0,%1,%2,%3}, {%4,%5,%6,%7}, {%8,%9}, {%0,%1,%2,%3};"
        : "+f"(d[0]), "+f"(d[1]), "+f"(d[2]), "+f"(d[3])
        : "r"(a[0]), "r"(a[1]), "r"(a[2]), "r"(a[3]), "r"(b[0]), "r"(b[1]));
}

__device__ __forceinline__ void cpa16(uint32_t dst, const void* src) {
    asm volatile("cp.async.cg.shared.global [%0], [%1], 16;" :: "r"(dst), "l"(src));
}
#define CPA_COMMIT() asm volatile("cp.async.commit_group;")
#define CPA_WAIT0()  asm volatile("cp.async.wait_group 0;" ::: "memory")
#define CPA_WAIT1()  asm volatile("cp.async.wait_group 1;" ::: "memory")

// ---------------------------------------------------------------------------
// fp16 rounding passes
// ---------------------------------------------------------------------------
__global__ void __launch_bounds__(256) round4h(const float* __restrict__ in,
                                               __half* __restrict__ out,
                                               int n4, float scale) {
    int i = blockIdx.x * blockDim.x + threadIdx.x;
    if (i < n4) {
        float4 v = ((const float4*)in)[i];
        __half2* o = (__half2*)out + i * 2;
        o[0] = __floats2half2_rn(v.x * scale, v.y * scale);
        o[1] = __floats2half2_rn(v.z * scale, v.w * scale);
    }
}

__global__ void __launch_bounds__(256) round4w(const float* __restrict__ w0,
                                               const float* __restrict__ w1,
                                               const float* __restrict__ w2,
                                               const float* __restrict__ w3,
                                               __half* __restrict__ out) {
    const float* src[4] = { w0, w1, w2, w3 };
    const float scl[4]  = { QSCALE, 1.f, 1.f, 1.f };
    int m = blockIdx.y;
    int i = blockIdx.x * blockDim.x + threadIdx.x;
    float s = scl[m];
    float4 v = ((const float4*)src[m])[i];
    __half2* o = (__half2*)(out + (size_t)m * DMODEL * DMODEL) + i * 2;
    o[0] = __floats2half2_rn(v.x * s, v.y * s);
    o[1] = __floats2half2_rn(v.z * s, v.w * s);
}

// ---------------------------------------------------------------------------
// V transpose per head: vT[h*64+d][t] = v[t][h*64+d]
// ---------------------------------------------------------------------------
__global__ void __launch_bounds__(256) vtrans(const __half* __restrict__ v,
                                              __half* __restrict__ vT) {
    __shared__ __half ts[64][72];
    const int t0 = blockIdx.x * 64;
    const int h  = blockIdx.y;
    const int tid = threadIdx.x;

#pragma unroll
    for (int p = 0; p < 2; p++) {
        int idx = p * 256 + tid;
        int t = idx >> 3, c16 = idx & 7;
        *(float4*)&ts[t][c16 * 8] =
            *(const float4*)(v + (size_t)(t0 + t) * DMODEL + h * DK + c16 * 8);
    }
    __syncthreads();
#pragma unroll
    for (int p = 0; p < 2; p++) {
        int idx = p * 256 + tid;
        int d = idx >> 3, c16 = idx & 7;
        __half tmp[8];
#pragma unroll
        for (int j = 0; j < 8; j++) tmp[j] = ts[c16 * 8 + j][d];
        *(float4*)(vT + (size_t)(h * DK + d) * S_LEN + t0 + c16 * 8) = *(const float4*)tmp;
    }
}

// ---------------------------------------------------------------------------
// NT GEMM fp16 (m16n8k16), 3-STAGE cp.async pipeline, z-batched B/C.
// Block 128x128x32, 8 warps 2(m)x4(n).
// ---------------------------------------------------------------------------
#define GBM 128
#define GBN 128
#define GBK 32
#define GLDH 40
#define GBUFH (GBM * GLDH)          // 5120 halfs per buffer
#define GSTAGES 3
#define GSMH (2 * GSTAGES * GBUFH * 2)   // 61440 bytes

template <bool OUTH>
__global__ void __launch_bounds__(256) gemm_h(const __half* __restrict__ A,
                                              const __half* __restrict__ Bbase,
                                              void* __restrict__ Cv,
                                              int M, int N, int K) {
    extern __shared__ __align__(16) __half smh[];
    const uint32_t sb = (uint32_t)__cvta_generic_to_shared(smh);

    const int tid  = threadIdx.x;
    const int warp = tid >> 5, lane = tid & 31;
    const int wm   = warp >> 2;
    const int wn   = warp & 3;
    const int g    = lane >> 2;
    const int tg   = lane & 3;
    const int bm   = blockIdx.y * GBM;
    const int bn   = blockIdx.x * GBN;
    const int z    = blockIdx.z;

    const __half* B = Bbase + (size_t)z * N * K;

    auto issue = [&](int c, int s) {
        const int k0 = c * GBK;
#pragma unroll
        for (int p = 0; p < 2; p++) {
            int idx = p * 256 + tid;
            int r = idx >> 2, c16 = idx & 3;
            cpa16(sb + (s * GBUFH + r * GLDH + c16 * 8) * 2,
                  A + (size_t)(bm + r) * K + k0 + c16 * 8);
            cpa16(sb + ((GSTAGES * GBUFH + s * GBUFH) + r * GLDH + c16 * 8) * 2,
                  B + (size_t)(bn + r) * K + k0 + c16 * 8);
        }
        CPA_COMMIT();
    };

    float acc[4][4][4];
#pragma unroll
    for (int mt = 0; mt < 4; mt++)
#pragma unroll
        for (int nt = 0; nt < 4; nt++)
#pragma unroll
            for (int i = 0; i < 4; i++) acc[mt][nt][i] = 0.f;

    const int NCHUNK = K / GBK;       // 32
    issue(0, 0);
    issue(1, 1);

    for (int c = 0; c < NCHUNK; c++) {
        CPA_WAIT1();                   // group c complete (newest may be pending)
        __syncthreads();
        if (c + 2 < NCHUNK) issue(c + 2, (c + 2) % GSTAGES);
        else                CPA_COMMIT();   // keep group counting valid

        const int s = c % GSTAGES;
        const uint32_t* Au = (const uint32_t*)(smh + s * GBUFH);
        const uint32_t* Bu = (const uint32_t*)(smh + GSTAGES * GBUFH + s * GBUFH);

#pragma unroll
        for (int ks = 0; ks < 2; ks++) {
            const int kb = ks * 8;
            uint32_t af[4][4], bf[4][2];
#pragma unroll
            for (int mt = 0; mt < 4; mt++) {
                int r = wm * 64 + mt * 16 + g;
                af[mt][0] = Au[r * 20 + kb + tg];
                af[mt][1] = Au[(r + 8) * 20 + kb + tg];
                af[mt][2] = Au[r * 20 + kb + tg + 4];
                af[mt][3] = Au[(r + 8) * 20 + kb + tg + 4];
            }
#pragma unroll
            for (int nt = 0; nt < 4; nt++) {
                int c2 = wn * 32 + nt * 8 + g;
                bf[nt][0] = Bu[c2 * 20 + kb + tg];
                bf[nt][1] = Bu[c2 * 20 + kb + tg + 4];
            }
#pragma unroll
            for (int mt = 0; mt < 4; mt++)
#pragma unroll
                for (int nt = 0; nt < 4; nt++) mma16(acc[mt][nt], af[mt], bf[nt]);
        }
    }

#pragma unroll
    for (int mt = 0; mt < 4; mt++)
#pragma unroll
        for (int nt = 0; nt < 4; nt++) {
            int r0 = bm + wm * 64 + mt * 16 + g;
            int c  = bn + wn * 32 + nt * 8 + 2 * tg;
            if (OUTH) {
                __half* C = (__half*)Cv + (size_t)z * M * N;
                *(__half2*)(C + (size_t)r0 * N + c) =
                    __floats2half2_rn(acc[mt][nt][0], acc[mt][nt][1]);
                *(__half2*)(C + (size_t)(r0 + 8) * N + c) =
                    __floats2half2_rn(acc[mt][nt][2], acc[mt][nt][3]);
            } else {
                float* C = (float*)Cv + (size_t)z * M * N;
                *(float2*)(C + (size_t)r0 * N + c)       = make_float2(acc[mt][nt][0], acc[mt][nt][1]);
                *(float2*)(C + (size_t)(r0 + 8) * N + c) = make_float2(acc[mt][nt][2], acc[mt][nt][3]);
            }
        }
}

// ---------------------------------------------------------------------------
// Flash attention fp16, P-in-registers, exp2 softmax (unchanged R11 winner)
// ---------------------------------------------------------------------------
#define BQ 128
#define BT 64
#define LDH 72
#define KBUF_H (BT * LDH)
#define VS_OFF_H (2 * KBUF_H)
#define ATTN_SMEM ((VS_OFF_H + 2 * KBUF_H) * 2)   // 36864 bytes

__global__ void __launch_bounds__(256, 2) attn_mma(const __half* __restrict__ Qg,
                                                   const __half* __restrict__ Kg,
                                                   const __half* __restrict__ VTg,
                                                   __half* __restrict__ Og) {
    extern __shared__ __align__(16) __half smh[];
    const uint32_t sb = (uint32_t)__cvta_generic_to_shared(smh);

    const int h   = blockIdx.y;
    const int q0  = blockIdx.x * BQ;
    const int tid = threadIdx.x;
    const int warp = tid >> 5, lane = tid & 31;
    const int g   = lane >> 2;
    const int tg  = lane & 3;
    const int hoff = h * DK;

    const int r0 = warp * 16 + g;
    const int r1 = r0 + 8;

    auto issue_kv = [&](int t0, int buf) {
#pragma unroll
        for (int p = 0; p < 2; p++) {
            int idx = p * 256 + tid;
            int r = idx >> 3, c16 = idx & 7;
            cpa16(sb + (buf * KBUF_H + r * LDH + c16 * 8) * 2,
                  Kg + (size_t)(t0 + r) * DMODEL + hoff + c16 * 8);
            cpa16(sb + ((VS_OFF_H + buf * KBUF_H) + r * LDH + c16 * 8) * 2,
                  VTg + (size_t)(hoff + r) * S_LEN + t0 + c16 * 8);
        }
        CPA_COMMIT();
    };

    issue_kv(0, 0);

    uint32_t qf[4][4];
    {
        const uint32_t* qu0 = (const uint32_t*)(Qg + (size_t)(q0 + r0) * DMODEL + hoff);
        const uint32_t* qu1 = (const uint32_t*)(Qg + (size_t)(q0 + r1) * DMODEL + hoff);
#pragma unroll
        for (int ks = 0; ks < 4; ks++) {
            qf[ks][0] = qu0[ks * 8 + tg];
            qf[ks][1] = qu1[ks * 8 + tg];
            qf[ks][2] = qu0[ks * 8 + tg + 4];
            qf[ks][3] = qu1[ks * 8 + tg + 4];
        }
    }

    float m0 = -1e30f, m1 = -1e30f, l0 = 0.f, l1 = 0.f;
    float oacc[8][4];
#pragma unroll
    for (int nt = 0; nt < 8; nt++)
#pragma unroll
        for (int i = 0; i < 4; i++) oacc[nt][i] = 0.f;

    int buf = 0;
    for (int t0 = 0; t0 < S_LEN; t0 += BT) {
        CPA_WAIT0();
        __syncthreads();
        if (t0 + BT < S_LEN) issue_kv(t0 + BT, buf ^ 1);

        const uint32_t* Ku = (const uint32_t*)(smh + buf * KBUF_H);
        const uint32_t* Vu = (const uint32_t*)(smh + VS_OFF_H + buf * KBUF_H);

        float accS[8][4];
#pragma unroll
        for (int nt = 0; nt < 8; nt++)
#pragma unroll
            for (int i = 0; i < 4; i++) accS[nt][i] = 0.f;

#pragma unroll
        for (int ks = 0; ks < 4; ks++) {
            const int kb = ks * 8;
#pragma unroll
            for (int nt = 0; nt < 8; nt++) {
                int t = nt * 8 + g;
                uint32_t b[2] = { Ku[t * 36 + kb + tg], Ku[t * 36 + kb + tg + 4] };
                mma16(accS[nt], qf[ks], b);
            }
        }

        float mx0 = -1e30f, mx1 = -1e30f;
#pragma unroll
        for (int nt = 0; nt < 8; nt++) {
            mx0 = fmaxf(mx0, fmaxf(accS[nt][0], accS[nt][1]));
            mx1 = fmaxf(mx1, fmaxf(accS[nt][2], accS[nt][3]));
        }
        mx0 = fmaxf(mx0, __shfl_xor_sync(0xffffffffu, mx0, 1));
        mx0 = fmaxf(mx0, __shfl_xor_sync(0xffffffffu, mx0, 2));
        mx1 = fmaxf(mx1, __shfl_xor_sync(0xffffffffu, mx1, 1));
        mx1 = fmaxf(mx1, __shfl_xor_sync(0xffffffffu, mx1, 2));

        float mn0 = fmaxf(m0, mx0), mn1 = fmaxf(m1, mx1);
        float c0 = exp2f(m0 - mn0), c1 = exp2f(m1 - mn1);
        m0 = mn0; m1 = mn1;

        uint32_t pa0[8], pa1[8];
        float ps0 = 0.f, ps1 = 0.f;
#pragma unroll
        for (int nt = 0; nt < 8; nt++) {
            float p00 = exp2f(accS[nt][0] - m0);
            float p01 = exp2f(accS[nt][1] - m0);
            float p10 = exp2f(accS[nt][2] - m1);
            float p11 = exp2f(accS[nt][3] - m1);
            ps0 += p00 + p01; ps1 += p10 + p11;
            __half2 h0 = __floats2half2_rn(p00, p01);
            __half2 h1 = __floats2half2_rn(p10, p11);
            pa0[nt] = *(uint32_t*)&h0;
            pa1[nt] = *(uint32_t*)&h1;
        }
        ps0 += __shfl_xor_sync(0xffffffffu, ps0, 1);
        ps0 += __shfl_xor_sync(0xffffffffu, ps0, 2);
        ps1 += __shfl_xor_sync(0xffffffffu, ps1, 1);
        ps1 += __shfl_xor_sync(0xffffffffu, ps1, 2);

        l0 = l0 * c0 + ps0;
        l1 = l1 * c1 + ps1;
#pragma unroll
        for (int nt = 0; nt < 8; nt++) {
            oacc[nt][0] *= c0; oacc[nt][1] *= c0;
            oacc[nt][2] *= c1; oacc[nt][3] *= c1;
        }

#pragma unroll
        for (int ks = 0; ks < 4; ks++) {
            const int kb = ks * 8;
            uint32_t af[4] = { pa0[2 * ks], pa1[2 * ks], pa0[2 * ks + 1], pa1[2 * ks + 1] };
#pragma unroll
            for (int nt = 0; nt < 8; nt++) {
                int d = nt * 8 + g;
                uint32_t b[2] = { Vu[d * 36 + kb + tg], Vu[d * 36 + kb + tg + 4] };
                mma16(oacc[nt], af, b);
            }
        }
        buf ^= 1;
    }

    float inv0 = 1.f / l0, inv1 = 1.f / l1;
#pragma unroll
    for (int nt = 0; nt < 8; nt++) {
        int c = hoff + nt * 8 + 2 * tg;
        *(__half2*)(Og + (size_t)(q0 + r0) * DMODEL + c) =
            __floats2half2_rn(oacc[nt][0] * inv0, oacc[nt][1] * inv0);
        *(__half2*)(Og + (size_t)(q0 + r1) * DMODEL + c) =
            __floats2half2_rn(oacc[nt][2] * inv1, oacc[nt][3] * inv1);
    }
}

// ---------------------------------------------------------------------------
extern "C" void kernel_launch(void* const* d_in, const int* in_sizes, int n_in,
                              void* d_out, int out_size) {
    const float* x  = (const float*)d_in[0];
    const float* Wq = (const float*)d_in[1];
    const float* Wk = (const float*)d_in[2];
    const float* Wv = (const float*)d_in[3];
    const float* Wo = (const float*)d_in[4];
    float* out = (float*)d_out;

    __half *qkv, *vT, *ao, *xr, *wr;
    cudaGetSymbolAddress((void**)&qkv, g_qkv);
    cudaGetSymbolAddress((void**)&vT,  g_vT);
    cudaGetSymbolAddress((void**)&ao,  g_ao);
    cudaGetSymbolAddress((void**)&xr,  g_xr);
    cudaGetSymbolAddress((void**)&wr,  g_wr);
    __half* q = qkv;
    __half* k = qkv + (size_t)S_LEN * DMODEL;
    __half* v = qkv + (size_t)2 * S_LEN * DMODEL;
    __half* wor = wr + (size_t)3 * DMODEL * DMODEL;

    cudaFuncSetAttribute(gemm_h<true>,
                         cudaFuncAttributeMaxDynamicSharedMemorySize, GSMH);
    cudaFuncSetAttribute(gemm_h<false>,
                         cudaFuncAttributeMaxDynamicSharedMemorySize, GSMH);
    cudaFuncSetAttribute(attn_mma,
                         cudaFuncAttributeMaxDynamicSharedMemorySize, ATTN_SMEM);

    round4h<<<(S_LEN * DMODEL / 4 + 255) / 256, 256>>>(x, xr, S_LEN * DMODEL / 4, 1.0f);
    round4w<<<dim3(DMODEL * DMODEL / 4 / 256, 4), 256>>>(Wq, Wk, Wv, Wo, wr);

    // QKV: one launch, z-batched over the 3 weight matrices
    gemm_h<true><<<dim3(DMODEL / GBN, S_LEN / GBM, 3), 256, GSMH>>>(
        xr, wr, qkv, S_LEN, DMODEL, DMODEL);

    vtrans<<<dim3(S_LEN / 64, NHEADS), 256>>>(v, vT);

    attn_mma<<<dim3(S_LEN / BQ, NHEADS), 256, ATTN_SMEM>>>(q, k, vT, ao);

    gemm_h<false><<<dim3(DMODEL / GBN, S_LEN / GBM, 1), 256, GSMH>>>(
        ao, wor, out, S_LEN, DMODEL, DMODEL);
}